// round 3
// baseline (speedup 1.0000x reference)
#include <cuda_runtime.h>
#include <math.h>

#define Bsz 64
#define Pn  2048
#define Ln  512
#define Hn  8
#define NC  16      // row-chunks per batch in flash pass
#define RPB (Pn/NC) // 128 rows per flash block
#define TR  8       // rows per smem tile

// ---------------- static scratch (no allocation) ----------------
__device__ float  g_qn [Bsz*Ln];
__device__ float  g_Q  [Bsz*Ln];
__device__ __align__(16) float g_gu [Bsz*Hn*Ln];
__device__ float  g_Sgu[Bsz*Hn];
__device__ float  g_bu [Bsz*Hn];
__device__ float4 g_A4 [(size_t)Bsz*NC*Hn*(Ln/4)];   // 16 MB partial accumulators
__device__ float4 g_msb[Bsz*NC*Hn];                  // (M, S, c, 0) per partial
__device__ float2 g_MS [Bsz*Hn];                     // final (M, 1/S)

// ---------------- K1: LN of query rows + init Q=0, out=res_b ----------------
__global__ void k1_ln_init(const float* __restrict__ xt,
                           const float* __restrict__ g, const float* __restrict__ b_,
                           const float* __restrict__ resb, float* __restrict__ outctx)
{
    int b = blockIdx.x, t = threadIdx.x;
    __shared__ float xs[Ln];
    __shared__ float red[16];
    __shared__ float stats[2];
    float2 v = ((const float2*)xt)[b*(Ln/2) + t];
    xs[2*t] = v.x; xs[2*t+1] = v.y;
    float s1 = v.x + v.y, s2 = v.x*v.x + v.y*v.y;
    #pragma unroll
    for (int o = 16; o; o >>= 1) {
        s1 += __shfl_xor_sync(~0u, s1, o);
        s2 += __shfl_xor_sync(~0u, s2, o);
    }
    int w = t >> 5, lane = t & 31;
    if (!lane) { red[w] = s1; red[8+w] = s2; }
    __syncthreads();
    if (!t) {
        float a = 0.f, c = 0.f;
        #pragma unroll
        for (int i = 0; i < 8; i++) { a += red[i]; c += red[8+i]; }
        float mean = a * (1.f/Ln);
        float var  = c * (1.f/Ln) - mean*mean;
        stats[0] = mean; stats[1] = rsqrtf(var + 1e-5f);
    }
    __syncthreads();
    float mean = stats[0], rstd = stats[1];
    #pragma unroll
    for (int l = t; l < Ln; l += 256) {
        g_qn[b*Ln + l]   = (xs[l] - mean) * rstd * g[l] + b_[l];
        outctx[b*Ln + l] = resb[l];
        g_Q[b*Ln + l]    = 0.f;
    }
}

// ---------------- K2: split-K GEMMs: Q = qn@W_q ; out += x_trafic@res_W ----------------
__global__ void k2_gemm(const float* __restrict__ xt,
                        const float* __restrict__ Wq, const float* __restrict__ Wr,
                        float* __restrict__ outctx)
{
    int kc = blockIdx.x, bg = blockIdx.y, mat = blockIdx.z;
    const float* X = mat ? xt : g_qn;
    const float* W = mat ? Wr : Wq;
    float* OUT     = mat ? outctx : g_Q;
    __shared__ float xsm[8*64];
    int t = threadIdx.x;
    xsm[t]       = X[(bg*8 + (t>>6))*Ln       + kc*64 + (t&63)];
    xsm[t + 256] = X[(bg*8 + ((t+256)>>6))*Ln + kc*64 + (t&63)];
    __syncthreads();
    float acc[16];
    #pragma unroll
    for (int i = 0; i < 16; i++) acc[i] = 0.f;
    int d0 = t, d1 = t + 256;
    #pragma unroll 4
    for (int kk = 0; kk < 64; kk++) {
        float w0 = W[(kc*64 + kk)*Ln + d0];
        float w1 = W[(kc*64 + kk)*Ln + d1];
        #pragma unroll
        for (int bb = 0; bb < 8; bb++) {
            float x = xsm[bb*64 + kk];
            acc[2*bb]   += x * w0;
            acc[2*bb+1] += x * w1;
        }
    }
    #pragma unroll
    for (int bb = 0; bb < 8; bb++) {
        atomicAdd(&OUT[(bg*8+bb)*Ln + d0], acc[2*bb]);
        atomicAdd(&OUT[(bg*8+bb)*Ln + d1], acc[2*bb+1]);
    }
}

// ---------------- K3: u = W_k_head . Q_head / 8; gu = g*u; Sgu, bu reductions ----------------
__global__ void k3_u(const float* __restrict__ Wk,
                     const float* __restrict__ lng, const float* __restrict__ lnb)
{
    int b = blockIdx.x;
    int t = threadIdx.x, w = t >> 5, lane = t & 31;
    __shared__ float Qs[Ln];
    __shared__ float wk[16*Ln];   // 32KB staging for 16 W_k rows
    __shared__ float red[16];
    if (t < 16) red[t] = 0.f;
    Qs[t] = g_Q[b*Ln + t];
    float accS = 0.f, accB = 0.f;
    __syncthreads();
    for (int tile = 0; tile < 32; tile++) {
        __syncthreads();
        const float4* src = (const float4*)(Wk + (size_t)tile*16*Ln);
        float4* dst = (float4*)wk;
        dst[t]        = src[t];
        dst[t + 512]  = src[t + 512];
        dst[t + 1024] = src[t + 1024];
        dst[t + 1536] = src[t + 1536];
        __syncthreads();
        int l = tile*16 + w;                 // warp w handles W_k row l
        const float* wrow = wk + w*Ln;
        float u[8];
        #pragma unroll
        for (int h = 0; h < 8; h++) {
            float2 a = ((const float2*)(wrow + h*64))[lane];
            float2 q = ((const float2*)(Qs   + h*64))[lane];
            float p = a.x*q.x + a.y*q.y;
            #pragma unroll
            for (int o = 16; o; o >>= 1) p += __shfl_xor_sync(~0u, p, o);
            u[h] = p * 0.125f;               // includes 1/sqrt(D_K)
        }
        float gl = lng[l], bl = lnb[l];
        #pragma unroll
        for (int h = 0; h < 8; h++) {
            if (lane == h) {                 // static indexing, no spill
                g_gu[(b*Hn + h)*Ln + l] = gl * u[h];
                accS += gl * u[h];
                accB += bl * u[h];
            }
        }
    }
    if (lane < 8) { atomicAdd(&red[lane], accS); atomicAdd(&red[8+lane], accB); }
    __syncthreads();
    if (t < 8)       g_Sgu[b*Hn + t]     = red[t];
    else if (t < 16) g_bu [b*Hn + t - 8] = red[t];
}

// ---------------- K4: flash pass over x_dynamic (dominant kernel) ----------------
__global__ void __launch_bounds__(256, 3) k4_flash(
    const float* __restrict__ xd, float* __restrict__ attn_scores)
{
    int b = blockIdx.x, chunk = blockIdx.y;
    int t = threadIdx.x, w = t >> 5, lane = t & 31;   // warp w == head w
    __shared__ float4 xs4[TR][Ln/4];
    __shared__ float2 rowstat[TR];

    float4 gu4[4];
    const float4* gub = (const float4*)g_gu + (size_t)(b*Hn + w)*(Ln/4);
    #pragma unroll
    for (int j = 0; j < 4; j++) gu4[j] = gub[j*32 + lane];
    float Sgu = g_Sgu[b*Hn + w], bu = g_bu[b*Hn + w];

    float M = -1e30f, S = 0.f, c = 0.f;
    float4 A[4];
    #pragma unroll
    for (int j = 0; j < 4; j++) A[j] = make_float4(0.f, 0.f, 0.f, 0.f);

    const size_t rowbase = (size_t)b*Pn + (size_t)chunk*RPB;
    float* scout = attn_scores + (size_t)(b*Hn + w)*Pn + chunk*RPB;

    for (int tile = 0; tile < RPB/TR; tile++) {
        __syncthreads();
        {   // load phase: warp w loads row tile*TR + w, computes its stats
            const float4* src = (const float4*)(xd + (rowbase + tile*TR + w)*Ln);
            float4 v[4]; float s1 = 0.f, s2 = 0.f;
            #pragma unroll
            for (int j = 0; j < 4; j++) {
                v[j] = src[j*32 + lane];
                s1 += v[j].x + v[j].y + v[j].z + v[j].w;
                s2 += v[j].x*v[j].x + v[j].y*v[j].y + v[j].z*v[j].z + v[j].w*v[j].w;
            }
            #pragma unroll
            for (int o = 16; o; o >>= 1) {
                s1 += __shfl_xor_sync(~0u, s1, o);
                s2 += __shfl_xor_sync(~0u, s2, o);
            }
            #pragma unroll
            for (int j = 0; j < 4; j++) xs4[w][j*32 + lane] = v[j];
            if (!lane) {
                float mean = s1 * (1.f/Ln);
                float var  = s2 * (1.f/Ln) - mean*mean;
                rowstat[w] = make_float2(mean, rsqrtf(var + 1e-5f));
            }
        }
        __syncthreads();
        float sc8[TR];
        #pragma unroll
        for (int r = 0; r < TR; r++) {
            float4 xv[4];
            float d = 0.f;
            #pragma unroll
            for (int j = 0; j < 4; j++) {
                xv[j] = xs4[r][j*32 + lane];
                d += xv[j].x*gu4[j].x + xv[j].y*gu4[j].y
                   + xv[j].z*gu4[j].z + xv[j].w*gu4[j].w;
            }
            #pragma unroll
            for (int o = 16; o; o >>= 1) d += __shfl_xor_sync(~0u, d, o);
            float2 st = rowstat[r];
            float score = st.y * (d - st.x*Sgu) + bu;
            sc8[r] = score;
            float e;
            if (score > M) {                 // warp-uniform branch
                float sc = __expf(M - score);
                S *= sc; c *= sc;
                #pragma unroll
                for (int j = 0; j < 4; j++) {
                    A[j].x *= sc; A[j].y *= sc; A[j].z *= sc; A[j].w *= sc;
                }
                M = score; e = 1.f;
            } else {
                e = __expf(score - M);
            }
            S += e;
            float cf = e * st.y;
            c += cf * st.x;
            #pragma unroll
            for (int j = 0; j < 4; j++) {
                A[j].x += cf*xv[j].x; A[j].y += cf*xv[j].y;
                A[j].z += cf*xv[j].z; A[j].w += cf*xv[j].w;
            }
        }
        if (!lane) {
            float4* so = (float4*)(scout + tile*TR);
            so[0] = make_float4(sc8[0], sc8[1], sc8[2], sc8[3]);
            so[1] = make_float4(sc8[4], sc8[5], sc8[6], sc8[7]);
        }
    }
    size_t pbase = ((size_t)(b*NC + chunk)*Hn + w)*(Ln/4);
    #pragma unroll
    for (int j = 0; j < 4; j++) g_A4[pbase + j*32 + lane] = A[j];
    if (!lane) g_msb[(b*NC + chunk)*Hn + w] = make_float4(M, S, c, 0.f);
}

// ---------------- K5: combine partials, wsum, ctx GEMV, add into out ----------------
__global__ void k5_reduce(const float* __restrict__ Wv,
                          const float* __restrict__ lng, const float* __restrict__ lnb,
                          float* __restrict__ outctx)
{
    int b = blockIdx.x, h = blockIdx.y;
    int t = threadIdx.x;   // 128 threads
    __shared__ float wsh[NC];
    __shared__ float sInvS, sC;
    __shared__ float ws[Ln];
    __shared__ float part[128];
    if (t == 0) {
        float Mg = -1e30f;
        #pragma unroll
        for (int i = 0; i < NC; i++) Mg = fmaxf(Mg, g_msb[(b*NC+i)*Hn + h].x);
        float Sg = 0.f, cg = 0.f;
        #pragma unroll
        for (int i = 0; i < NC; i++) {
            float4 m = g_msb[(b*NC+i)*Hn + h];
            float wgt = __expf(m.x - Mg);
            wsh[i] = wgt; Sg += wgt*m.y; cg += wgt*m.z;
        }
        sInvS = 1.f/Sg; sC = cg;
        g_MS[b*Hn + h] = make_float2(Mg, 1.f/Sg);
    }
    __syncthreads();
    float invS = sInvS, cg = sC;
    {
        int v = t;   // one float4 per thread: 128 x 4 = 512 floats, exactly Ln
        float4 acc = make_float4(0.f, 0.f, 0.f, 0.f);
        for (int i = 0; i < NC; i++) {
            float4 a = g_A4[((size_t)(b*NC+i)*Hn + h)*(Ln/4) + v];
            float wgt = wsh[i];
            acc.x += wgt*a.x; acc.y += wgt*a.y; acc.z += wgt*a.z; acc.w += wgt*a.w;
        }
        float4 g4 = ((const float4*)lng)[v], b4 = ((const float4*)lnb)[v];
        ws[4*v+0] = g4.x*(acc.x - cg)*invS + b4.x;
        ws[4*v+1] = g4.y*(acc.y - cg)*invS + b4.y;
        ws[4*v+2] = g4.z*(acc.z - cg)*invS + b4.z;
        ws[4*v+3] = g4.w*(acc.w - cg)*invS + b4.w;
    }
    __syncthreads();
    int d = t & 63, half = t >> 6;
    float acc = 0.f;
    #pragma unroll 4
    for (int l = half*256; l < half*256 + 256; l++)
        acc += ws[l] * Wv[l*Ln + h*64 + d];
    part[t] = acc;
    __syncthreads();
    if (t < 64) outctx[b*Ln + h*64 + t] += part[t] + part[64 + t];
}

// ---------------- K6: normalize scores -> attn ----------------
__global__ void k6_norm(float* __restrict__ attn)
{
    int i  = blockIdx.x*256 + threadIdx.x;   // float4 index, 262144 total
    int bh = i >> 9;                         // 512 float4 per (b,h)
    float2 MS = g_MS[bh];
    float4 s = ((float4*)attn)[i];
    s.x = __expf(s.x - MS.x)*MS.y;
    s.y = __expf(s.y - MS.x)*MS.y;
    s.z = __expf(s.z - MS.x)*MS.y;
    s.w = __expf(s.w - MS.x)*MS.y;
    ((float4*)attn)[i] = s;
}

extern "C" void kernel_launch(void* const* d_in, const int* in_sizes, int n_in,
                              void* d_out, int out_size)
{
    const float* xt   = (const float*)d_in[0];
    const float* xd   = (const float*)d_in[1];
    // d_in[2] = x_known: unused by the reference computation
    const float* Wq   = (const float*)d_in[3];
    const float* Wk   = (const float*)d_in[4];
    const float* Wv   = (const float*)d_in[5];
    const float* lnqg = (const float*)d_in[6];
    const float* lnqb = (const float*)d_in[7];
    const float* lnkg = (const float*)d_in[8];
    const float* lnkb = (const float*)d_in[9];
    const float* Wr   = (const float*)d_in[10];
    const float* resb = (const float*)d_in[11];
    float* out  = (float*)d_out;
    float* attn = out + Bsz*Ln;   // context first, then attn (flattened tuple)

    k1_ln_init<<<Bsz, 256>>>(xt, lnqg, lnqb, resb, out);
    k2_gemm<<<dim3(8,8,2), 256>>>(xt, Wq, Wr, out);
    k3_u<<<Bsz, 512>>>(Wk, lnkg, lnkb);
    k4_flash<<<dim3(Bsz, NC), 256>>>(xd, attn);
    k5_reduce<<<dim3(Bsz, Hn), 128>>>(Wv, lnkg, lnkb, out);
    k6_norm<<<1024, 256>>>(attn);
}

// round 4
// speedup vs baseline: 1.2575x; 1.2575x over previous
#include <cuda_runtime.h>
#include <math.h>

#define Bsz 64
#define Pn  2048
#define Ln  512
#define Hn  8
#define NC  16      // row-chunks per batch in flash pass
#define RPB (Pn/NC) // 128 rows per flash block
#define TR  8       // rows per smem stage

typedef unsigned long long u64;

// ---------------- static scratch (no allocation) ----------------
__device__ float  g_qn [Bsz*Ln];
__device__ float  g_Q  [Bsz*Ln];
__device__ __align__(16) float g_gu [Bsz*Hn*Ln];
__device__ float  g_Sgu[Bsz*Hn];
__device__ float  g_bu [Bsz*Hn];
__device__ float4 g_A4 [(size_t)Bsz*NC*Hn*(Ln/4)];   // partial accumulators
__device__ float4 g_msb[Bsz*NC*Hn];                  // (M, S, c, 0) per partial
__device__ float2 g_MS [Bsz*Hn];                     // final (M, 1/S)

// ---------------- packed f32x2 helpers ----------------
__device__ __forceinline__ u64 pk2(float lo, float hi) {
    u64 r; asm("mov.b64 %0, {%1,%2};" : "=l"(r) : "f"(lo), "f"(hi)); return r;
}
__device__ __forceinline__ void upk2(u64 v, float& lo, float& hi) {
    asm("mov.b64 {%0,%1}, %2;" : "=f"(lo), "=f"(hi) : "l"(v));
}
__device__ __forceinline__ u64 fma2(u64 a, u64 b, u64 c) {
    u64 r; asm("fma.rn.f32x2 %0, %1, %2, %3;" : "=l"(r) : "l"(a), "l"(b), "l"(c)); return r;
}
__device__ __forceinline__ u64 mul2(u64 a, u64 b) {
    u64 r; asm("mul.rn.f32x2 %0, %1, %2;" : "=l"(r) : "l"(a), "l"(b)); return r;
}
__device__ __forceinline__ u64 add2(u64 a, u64 b) {
    u64 r; asm("add.rn.f32x2 %0, %1, %2;" : "=l"(r) : "l"(a), "l"(b)); return r;
}

// ---------------- cp.async helpers ----------------
__device__ __forceinline__ void cpasync16(void* smem, const void* g) {
    unsigned s = (unsigned)__cvta_generic_to_shared(smem);
    asm volatile("cp.async.cg.shared.global [%0], [%1], 16;" :: "r"(s), "l"(g));
}
#define CP_COMMIT()  asm volatile("cp.async.commit_group;")
#define CP_WAIT(N)   asm volatile("cp.async.wait_group %0;" :: "n"(N))

// ---------------- K1: LN of query rows + init ----------------
__global__ void k1_ln_init(const float* __restrict__ xt,
                           const float* __restrict__ g, const float* __restrict__ b_,
                           const float* __restrict__ resb, float* __restrict__ outctx)
{
    int b = blockIdx.x, t = threadIdx.x;
    __shared__ float xs[Ln];
    __shared__ float red[16];
    __shared__ float stats[2];
    float2 v = ((const float2*)xt)[b*(Ln/2) + t];
    xs[2*t] = v.x; xs[2*t+1] = v.y;
    float s1 = v.x + v.y, s2 = v.x*v.x + v.y*v.y;
    #pragma unroll
    for (int o = 16; o; o >>= 1) {
        s1 += __shfl_xor_sync(~0u, s1, o);
        s2 += __shfl_xor_sync(~0u, s2, o);
    }
    int w = t >> 5, lane = t & 31;
    if (!lane) { red[w] = s1; red[8+w] = s2; }
    __syncthreads();
    if (!t) {
        float a = 0.f, c = 0.f;
        #pragma unroll
        for (int i = 0; i < 8; i++) { a += red[i]; c += red[8+i]; }
        float mean = a * (1.f/Ln);
        float var  = c * (1.f/Ln) - mean*mean;
        stats[0] = mean; stats[1] = rsqrtf(var + 1e-5f);
    }
    __syncthreads();
    float mean = stats[0], rstd = stats[1];
    #pragma unroll
    for (int l = t; l < Ln; l += 256) {
        g_qn[b*Ln + l]   = (xs[l] - mean) * rstd * g[l] + b_[l];
        outctx[b*Ln + l] = resb[l];
        g_Q[b*Ln + l]    = 0.f;
    }
    if (t < 8) { g_Sgu[b*8 + t] = 0.f; g_bu[b*8 + t] = 0.f; }
}

// ---------------- K2: split-K GEMMs: Q = qn@W_q ; out += x_trafic@res_W ----------------
__global__ void k2_gemm(const float* __restrict__ xt,
                        const float* __restrict__ Wq, const float* __restrict__ Wr,
                        float* __restrict__ outctx)
{
    int kc = blockIdx.x, bg = blockIdx.y, mat = blockIdx.z;
    const float* X = mat ? xt : g_qn;
    const float* W = mat ? Wr : Wq;
    float* OUT     = mat ? outctx : g_Q;
    __shared__ float xsm[8*64];
    int t = threadIdx.x;
    xsm[t]       = X[(bg*8 + (t>>6))*Ln       + kc*64 + (t&63)];
    xsm[t + 256] = X[(bg*8 + ((t+256)>>6))*Ln + kc*64 + (t&63)];
    __syncthreads();
    float acc[16];
    #pragma unroll
    for (int i = 0; i < 16; i++) acc[i] = 0.f;
    int d0 = t, d1 = t + 256;
    #pragma unroll 4
    for (int kk = 0; kk < 64; kk++) {
        float w0 = W[(kc*64 + kk)*Ln + d0];
        float w1 = W[(kc*64 + kk)*Ln + d1];
        #pragma unroll
        for (int bb = 0; bb < 8; bb++) {
            float x = xsm[bb*64 + kk];
            acc[2*bb]   += x * w0;
            acc[2*bb+1] += x * w1;
        }
    }
    #pragma unroll
    for (int bb = 0; bb < 8; bb++) {
        atomicAdd(&OUT[(bg*8+bb)*Ln + d0], acc[2*bb]);
        atomicAdd(&OUT[(bg*8+bb)*Ln + d1], acc[2*bb+1]);
    }
}

// ---------------- K3 v2: tiled mini-GEMM  u[b,h,l] = (1/8) Wk_row(l,head h) . Q(b,head h) ----------------
// grid (32 l-tiles of 16, 16 b-groups of 4), 128 threads: t -> (h = t>>4, l = t&15)
__global__ void k3_u(const float* __restrict__ Wk, const float* __restrict__ Q_unused,
                     const float* __restrict__ lng, const float* __restrict__ lnb)
{
    int lt = blockIdx.x, bg = blockIdx.y;
    int l0 = lt*16, b0 = bg*4;
    int t = threadIdx.x;
    int l = t & 15, h = t >> 4;
    __shared__ float4 Wks[16*128];   // 16 rows x 512 floats
    __shared__ float4 Qs [4*128];    // 4 rows x 512 floats

    // stage Wk rows (coalesced)
    const float4* wsrc = (const float4*)(Wk + (size_t)l0*Ln);
    #pragma unroll
    for (int k = 0; k < 16; k++) Wks[t + k*128] = wsrc[t + k*128];
    const float4* qsrc = (const float4*)(g_Q + (size_t)b0*Ln);
    #pragma unroll
    for (int k = 0; k < 4; k++) Qs[t + k*128] = qsrc[t + k*128];
    __syncthreads();

    // thread-private W segment: row l, head h = 16 float4
    float4 wr[16];
    #pragma unroll
    for (int k = 0; k < 16; k++) wr[k] = Wks[l*128 + h*16 + k];

    float gl = lng[l0 + l], bl = lnb[l0 + l];

    #pragma unroll
    for (int bb = 0; bb < 4; bb++) {
        float acc = 0.f;
        #pragma unroll
        for (int k = 0; k < 16; k++) {
            float4 q = Qs[bb*128 + h*16 + k];
            acc += wr[k].x*q.x + wr[k].y*q.y + wr[k].z*q.z + wr[k].w*q.w;
        }
        float u = acc * 0.125f;     // includes 1/sqrt(D_K)
        float guv = gl * u;
        g_gu[((size_t)(b0+bb)*Hn + h)*Ln + l0 + l] = guv;
        float sS = guv, sB = bl * u;
        #pragma unroll
        for (int o = 8; o; o >>= 1) {
            sS += __shfl_xor_sync(~0u, sS, o);
            sB += __shfl_xor_sync(~0u, sB, o);
        }
        if (l == 0) {
            atomicAdd(&g_Sgu[(b0+bb)*Hn + h], sS);
            atomicAdd(&g_bu [(b0+bb)*Hn + h], sB);
        }
    }
}

// ---------------- K4 v2: flash pass, cp.async double-buffered + packed f32x2 ----------------
__global__ void __launch_bounds__(256, 3) k4_flash(
    const float* __restrict__ xd, float* __restrict__ attn_scores)
{
    int b = blockIdx.x, chunk = blockIdx.y;
    int t = threadIdx.x, w = t >> 5, lane = t & 31;   // warp w == head w
    __shared__ float4 xs4[2][TR][Ln/4];
    __shared__ float2 rowstat[TR];

    // per-warp gu in packed registers
    u64 gu2[8];
    {
        const float4* gub = (const float4*)g_gu + (size_t)(b*Hn + w)*(Ln/4);
        #pragma unroll
        for (int j = 0; j < 4; j++) {
            float4 g4 = gub[j*32 + lane];
            gu2[2*j]   = pk2(g4.x, g4.y);
            gu2[2*j+1] = pk2(g4.z, g4.w);
        }
    }
    float Sgu = g_Sgu[b*Hn + w], bu = g_bu[b*Hn + w];

    float M = -1e30f, S = 0.f, c = 0.f;
    u64 A2[8];
    #pragma unroll
    for (int j = 0; j < 8; j++) A2[j] = 0ull;

    const size_t rowbase = (size_t)b*Pn + (size_t)chunk*RPB;
    float* scout = attn_scores + (size_t)(b*Hn + w)*Pn + chunk*RPB;

    // prefetch tile 0
    {
        const float4* src = (const float4*)(xd + (rowbase)*Ln);
        #pragma unroll
        for (int k = 0; k < 4; k++) {
            int idx = t + k*256;
            cpasync16(&xs4[0][idx>>7][idx&127], &src[idx]);
        }
        CP_COMMIT();
    }

    int st = 0;
    for (int tile = 0; tile < RPB/TR; tile++) {
        if (tile + 1 < RPB/TR) {
            const float4* src = (const float4*)(xd + (rowbase + (size_t)(tile+1)*TR)*Ln);
            #pragma unroll
            for (int k = 0; k < 4; k++) {
                int idx = t + k*256;
                cpasync16(&xs4[st^1][idx>>7][idx&127], &src[idx]);
            }
            CP_COMMIT();
            CP_WAIT(1);
        } else {
            CP_WAIT(0);
        }
        __syncthreads();

        // ---- stats phase: warp w computes stats of row w ----
        {
            const float4* xr = xs4[st][w];
            u64 s1 = 0ull, s2 = 0ull;
            #pragma unroll
            for (int j = 0; j < 4; j++) {
                float4 v = xr[j*32 + lane];
                u64 a = pk2(v.x, v.y), bb2 = pk2(v.z, v.w);
                s1 = add2(s1, a); s1 = add2(s1, bb2);
                s2 = fma2(a, a, s2); s2 = fma2(bb2, bb2, s2);
            }
            float l1, h1, l2, h2;
            upk2(s1, l1, h1); upk2(s2, l2, h2);
            float f1 = l1 + h1, f2 = l2 + h2;
            float s  = (lane & 1) ? f2 : f1;
            float so = (lane & 1) ? f1 : f2;
            s += __shfl_xor_sync(~0u, so, 1);
            s += __shfl_xor_sync(~0u, s, 2);
            s += __shfl_xor_sync(~0u, s, 4);
            s += __shfl_xor_sync(~0u, s, 8);
            s += __shfl_xor_sync(~0u, s, 16);
            float sum2 = __shfl_sync(~0u, s, 1);
            if (!lane) {
                float mean = s * (1.f/Ln);
                float var  = sum2 * (1.f/Ln) - mean*mean;
                rowstat[w] = make_float2(mean, rsqrtf(var + 1e-5f));
            }
        }
        __syncthreads();

        // ---- compute phase: 4 row-pairs ----
        float sc8[TR];
        #pragma unroll
        for (int p = 0; p < 4; p++) {
            const int r0 = 2*p, r1 = 2*p + 1;
            u64 a0[8], a1[8];
            {
                const float4* x0 = xs4[st][r0];
                const float4* x1 = xs4[st][r1];
                #pragma unroll
                for (int j = 0; j < 4; j++) {
                    float4 v0 = x0[j*32 + lane];
                    float4 v1 = x1[j*32 + lane];
                    a0[2*j] = pk2(v0.x, v0.y); a0[2*j+1] = pk2(v0.z, v0.w);
                    a1[2*j] = pk2(v1.x, v1.y); a1[2*j+1] = pk2(v1.z, v1.w);
                }
            }
            u64 d0 = 0ull, d1 = 0ull;
            #pragma unroll
            for (int k = 0; k < 8; k++) {
                d0 = fma2(a0[k], gu2[k], d0);
                d1 = fma2(a1[k], gu2[k], d1);
            }
            float l0f, h0f, l1f, h1f;
            upk2(d0, l0f, h0f); upk2(d1, l1f, h1f);
            float f0 = l0f + h0f, f1 = l1f + h1f;
            float s  = (lane & 1) ? f1 : f0;
            float so = (lane & 1) ? f0 : f1;
            s += __shfl_xor_sync(~0u, so, 1);
            s += __shfl_xor_sync(~0u, s, 2);
            s += __shfl_xor_sync(~0u, s, 4);
            s += __shfl_xor_sync(~0u, s, 8);
            s += __shfl_xor_sync(~0u, s, 16);
            float D0 = __shfl_sync(~0u, s, 0);
            float D1 = __shfl_sync(~0u, s, 1);

            #pragma unroll
            for (int q = 0; q < 2; q++) {
                float D = q ? D1 : D0;
                int r = q ? r1 : r0;
                float2 stt = rowstat[r];
                float score = stt.y * (D - stt.x*Sgu) + bu;
                sc8[r] = score;
                float e;
                if (score > M) {                 // warp-uniform branch
                    float sc = __expf(M - score);
                    S *= sc; c *= sc;
                    u64 sc2 = pk2(sc, sc);
                    #pragma unroll
                    for (int k = 0; k < 8; k++) A2[k] = mul2(A2[k], sc2);
                    M = score; e = 1.f;
                } else {
                    e = __expf(score - M);
                }
                S += e;
                float cf = e * stt.y;
                c += cf * stt.x;
                u64 cf2 = pk2(cf, cf);
                if (q) {
                    #pragma unroll
                    for (int k = 0; k < 8; k++) A2[k] = fma2(cf2, a1[k], A2[k]);
                } else {
                    #pragma unroll
                    for (int k = 0; k < 8; k++) A2[k] = fma2(cf2, a0[k], A2[k]);
                }
            }
        }
        if (!lane) {
            float4* so4 = (float4*)(scout + tile*TR);
            so4[0] = make_float4(sc8[0], sc8[1], sc8[2], sc8[3]);
            so4[1] = make_float4(sc8[4], sc8[5], sc8[6], sc8[7]);
        }
        st ^= 1;
    }

    size_t pbase = ((size_t)(b*NC + chunk)*Hn + w)*(Ln/4);
    #pragma unroll
    for (int j = 0; j < 4; j++) {
        float x0, x1, x2, x3;
        upk2(A2[2*j], x0, x1); upk2(A2[2*j+1], x2, x3);
        g_A4[pbase + j*32 + lane] = make_float4(x0, x1, x2, x3);
    }
    if (!lane) g_msb[(b*NC + chunk)*Hn + w] = make_float4(M, S, c, 0.f);
}

// ---------------- K5: combine partials, wsum, ctx GEMV, add into out ----------------
__global__ void k5_reduce(const float* __restrict__ Wv,
                          const float* __restrict__ lng, const float* __restrict__ lnb,
                          float* __restrict__ outctx)
{
    int b = blockIdx.x, h = blockIdx.y;
    int t = threadIdx.x;   // 128 threads
    __shared__ float wsh[NC];
    __shared__ float sInvS, sC;
    __shared__ float ws[Ln];
    __shared__ float part[128];
    if (t == 0) {
        float Mg = -1e30f;
        #pragma unroll
        for (int i = 0; i < NC; i++) Mg = fmaxf(Mg, g_msb[(b*NC+i)*Hn + h].x);
        float Sg = 0.f, cg = 0.f;
        #pragma unroll
        for (int i = 0; i < NC; i++) {
            float4 m = g_msb[(b*NC+i)*Hn + h];
            float wgt = __expf(m.x - Mg);
            wsh[i] = wgt; Sg += wgt*m.y; cg += wgt*m.z;
        }
        sInvS = 1.f/Sg; sC = cg;
        g_MS[b*Hn + h] = make_float2(Mg, 1.f/Sg);
    }
    __syncthreads();
    float invS = sInvS, cg = sC;
    {
        int v = t;   // one float4 per thread: 128 x 4 = 512 floats = Ln
        float4 acc = make_float4(0.f, 0.f, 0.f, 0.f);
        for (int i = 0; i < NC; i++) {
            float4 a = g_A4[((size_t)(b*NC+i)*Hn + h)*(Ln/4) + v];
            float wgt = wsh[i];
            acc.x += wgt*a.x; acc.y += wgt*a.y; acc.z += wgt*a.z; acc.w += wgt*a.w;
        }
        float4 g4 = ((const float4*)lng)[v], b4 = ((const float4*)lnb)[v];
        ws[4*v+0] = g4.x*(acc.x - cg)*invS + b4.x;
        ws[4*v+1] = g4.y*(acc.y - cg)*invS + b4.y;
        ws[4*v+2] = g4.z*(acc.z - cg)*invS + b4.z;
        ws[4*v+3] = g4.w*(acc.w - cg)*invS + b4.w;
    }
    __syncthreads();
    int d = t & 63, half = t >> 6;
    float acc = 0.f;
    #pragma unroll 4
    for (int l = half*256; l < half*256 + 256; l++)
        acc += ws[l] * Wv[l*Ln + h*64 + d];
    part[t] = acc;
    __syncthreads();
    if (t < 64) outctx[b*Ln + h*64 + t] += part[t] + part[64 + t];
}

// ---------------- K6: normalize scores -> attn ----------------
__global__ void k6_norm(float* __restrict__ attn)
{
    int i  = blockIdx.x*256 + threadIdx.x;   // float4 index, 262144 total
    int bh = i >> 9;                         // 512 float4 per (b,h)
    float2 MS = g_MS[bh];
    float4 s = ((float4*)attn)[i];
    s.x = __expf(s.x - MS.x)*MS.y;
    s.y = __expf(s.y - MS.x)*MS.y;
    s.z = __expf(s.z - MS.x)*MS.y;
    s.w = __expf(s.w - MS.x)*MS.y;
    ((float4*)attn)[i] = s;
}

extern "C" void kernel_launch(void* const* d_in, const int* in_sizes, int n_in,
                              void* d_out, int out_size)
{
    const float* xt   = (const float*)d_in[0];
    const float* xd   = (const float*)d_in[1];
    // d_in[2] = x_known: unused by the reference computation
    const float* Wq   = (const float*)d_in[3];
    const float* Wk   = (const float*)d_in[4];
    const float* Wv   = (const float*)d_in[5];
    const float* lnqg = (const float*)d_in[6];
    const float* lnqb = (const float*)d_in[7];
    const float* lnkg = (const float*)d_in[8];
    const float* lnkb = (const float*)d_in[9];
    const float* Wr   = (const float*)d_in[10];
    const float* resb = (const float*)d_in[11];
    float* out  = (float*)d_out;
    float* attn = out + Bsz*Ln;   // context first, then attn (flattened tuple)

    k1_ln_init<<<Bsz, 256>>>(xt, lnqg, lnqb, resb, out);
    k2_gemm<<<dim3(8,8,2), 256>>>(xt, Wq, Wr, out);
    k3_u<<<dim3(32,16), 128>>>(Wk, nullptr, lnkg, lnkb);
    k4_flash<<<dim3(Bsz, NC), 256>>>(xd, attn);
    k5_reduce<<<dim3(Bsz, Hn), 128>>>(Wv, lnkg, lnkb, out);
    k6_norm<<<1024, 256>>>(attn);
}